// round 9
// baseline (speedup 1.0000x reference)
#include <cuda_runtime.h>

// Problem constants
#define BB      64      // batch
#define HL      8       // hat_L
#define NPTS    16      // N
#define DDIM    32      // d
#define FLAYER  512     // N*d
#define FTOT    4096    // hat_L*N*d
#define NCHUNK  16      // feature chunks per layer == nodes (CF == DDIM)
#define NBLK    176     // grid size (all co-resident)
// phase-1: 0..127 gram+cov (t,nn), 128..135 sca, 136..175 idle
// phase-2: 0..127 sfa, 128..175 fused Wnum+exo (type,seg)

// -------- device scratch (no allocations allowed) --------
__device__ float g_P[3 * HL * NCHUNK * 4096];        // chunk Gram partials : 6 MB
__device__ float g_C[2][HL * NPTS * DDIM * DDIM];    // node covariances /63
__device__ float g_Wpart[48 * 8];                    // per-(type,seg) per-layer norm partials
__device__ float g_exo_part[48];                     // per-(type,seg) exo norm partials
__device__ float g_sca[HL];
__device__ float g_sfa[HL * NPTS];
__device__ unsigned int g_barcnt;                    // monotonic barrier ticket
__device__ unsigned int g_done;                      // completion ticket

// Closed-form 16x16 tile-grid triangle enumerations (exact fp32 at boundaries:
// the radicands at segment starts are squares of half-integers / odd integers).
__device__ __forceinline__ void upper_from_idx(int idx, int& r, int& c) {
    float rf = 16.5f - sqrtf(272.25f - 2.0f * (float)idx);
    r = (int)rf;
    c = r + idx - (16 * r - (r * (r - 1)) / 2);
}
__device__ __forceinline__ void lower_from_idx(int idx, int& r, int& c) {
    float rf = (1.0f + sqrtf(1.0f + 8.0f * (float)idx)) * 0.5f;
    r = (int)rf;
    c = idx - (r * (r - 1)) / 2;
}

// Replay-safe grid barrier: monotonic ticket counter, no reset needed.
__device__ __forceinline__ void grid_barrier() {
    __syncthreads();
    if (threadIdx.x == 0) {
        __threadfence();
        unsigned int ticket = atomicAdd(&g_barcnt, 1u);
        unsigned int target = (ticket / NBLK + 1u) * NBLK;
        while (true) {
            unsigned int v;
            asm volatile("ld.acquire.gpu.u32 %0, [%1];"
                         : "=r"(v) : "l"(&g_barcnt));
            if ((int)(v - target) >= 0) break;
            __nanosleep(32);
        }
    }
    __syncthreads();
}

__global__ void __launch_bounds__(256, 2) fused_all(
        const float* __restrict__ Zs, const float* __restrict__ Es,
        const float* __restrict__ Zt, const float* __restrict__ Et,
        float* __restrict__ out) {
    int blk = blockIdx.x, tid = threadIdx.x;

    __shared__ __align__(16) float St_s[DDIM][68];   // [f][b] transposed, padded
    __shared__ __align__(16) float St_t[DDIM][68];
    __shared__ float sm_ps[DDIM * 8], sm_pt[DDIM * 8];   // mean partials
    __shared__ float sm_ms[DDIM], sm_mt[DDIM];           // means
    __shared__ float red[256];
    __shared__ float sm_st[16], sm_tt[16], sm_ss;
    __shared__ float smr[8][9];
    __shared__ float smP[256][9];                    // element x layer exchange (phase 2)
    __shared__ unsigned int sm_last;

    // ================= PHASE 1 =================
    if (blk < 128) {
        // slice (t, nn): 64 batch x 32 features, load + center into St (transposed)
        int t = blk >> 4, nn = blk & 15;
        int fbase = t * FLAYER + nn * DDIM;
        int f0 = tid & 31, b0 = tid >> 5;
        float ps = 0.f, pt = 0.f;
        #pragma unroll
        for (int j = 0; j < 8; j++) {
            int b = b0 + 8 * j;
            float vs = Zs[b * FTOT + fbase + f0];
            float vt = Zt[b * FTOT + fbase + f0];
            St_s[f0][b] = vs; ps += vs;
            St_t[f0][b] = vt; pt += vt;
        }
        sm_ps[f0 * 8 + b0] = ps;
        sm_pt[f0 * 8 + b0] = pt;
        __syncthreads();
        if (tid < 64) {                       // reduce mean partials
            int f = tid & 31;
            float* P = (tid < 32) ? sm_ps : sm_pt;
            float m = 0.f;
            #pragma unroll
            for (int j = 0; j < 8; j++) m += P[f * 8 + j];
            m *= (1.0f / (float)BB);
            if (tid < 32) sm_ms[f] = m; else sm_mt[f] = m;
        }
        __syncthreads();
        {                                      // subtract means
            float ms = sm_ms[f0], mt = sm_mt[f0];
            #pragma unroll
            for (int j = 0; j < 8; j++) {
                int b = b0 + 8 * j;
                St_s[f0][b] -= ms;
                St_t[f0][b] -= mt;
            }
        }
        __syncthreads();

        float* p0 = &g_P[((0 * HL + t) * NCHUNK + nn) * 4096];
        float* p1 = &g_P[((1 * HL + t) * NCHUNK + nn) * 4096];
        float* p2 = &g_P[((2 * HL + t) * NCHUNK + nn) * 4096];
        int w = tid >> 5;

        if (w < 5) {
            // ---- 3-type 4x4 tile: 136 upper tiles + 24 padding (lower, st-store-only) ----
            int r, c;
            bool is_upper = (tid < 136);
            if (is_upper) upper_from_idx(tid, r, c);
            else          lower_from_idx(tid - 136, r, c);

            float a_ss[4][4] = {}, a_tt[4][4] = {}, a_st[4][4] = {};
            #pragma unroll 4
            for (int f = 0; f < DDIM; f++) {
                float4 v;
                float As[4], Bs[4], At[4], Bt[4];
                v = *(const float4*)&St_s[f][4 * r]; As[0]=v.x; As[1]=v.y; As[2]=v.z; As[3]=v.w;
                v = *(const float4*)&St_s[f][4 * c]; Bs[0]=v.x; Bs[1]=v.y; Bs[2]=v.z; Bs[3]=v.w;
                v = *(const float4*)&St_t[f][4 * r]; At[0]=v.x; At[1]=v.y; At[2]=v.z; At[3]=v.w;
                v = *(const float4*)&St_t[f][4 * c]; Bt[0]=v.x; Bt[1]=v.y; Bt[2]=v.z; Bt[3]=v.w;
                #pragma unroll
                for (int i = 0; i < 4; i++)
                    #pragma unroll
                    for (int j = 0; j < 4; j++) {
                        a_ss[i][j] += As[i] * Bs[j];
                        a_tt[i][j] += At[i] * Bt[j];
                        a_st[i][j] += As[i] * Bt[j];
                    }
            }
            // st stored always (st not symmetric; padding slots own their lower tile)
            #pragma unroll
            for (int i = 0; i < 4; i++)
                *(float4*)&p2[(4 * r + i) * 64 + 4 * c] =
                    make_float4(a_st[i][0], a_st[i][1], a_st[i][2], a_st[i][3]);
            if (is_upper) {
                #pragma unroll
                for (int i = 0; i < 4; i++) {
                    int o = (4 * r + i) * 64 + 4 * c;
                    *(float4*)&p0[o] = make_float4(a_ss[i][0], a_ss[i][1], a_ss[i][2], a_ss[i][3]);
                    *(float4*)&p1[o] = make_float4(a_tt[i][0], a_tt[i][1], a_tt[i][2], a_tt[i][3]);
                }
                if (r < c) {                   // mirror (bitwise-equal values)
                    #pragma unroll
                    for (int j = 0; j < 4; j++) {
                        int o = (4 * c + j) * 64 + 4 * r;
                        *(float4*)&p0[o] = make_float4(a_ss[0][j], a_ss[1][j], a_ss[2][j], a_ss[3][j]);
                        *(float4*)&p1[o] = make_float4(a_tt[0][j], a_tt[1][j], a_tt[2][j], a_tt[3][j]);
                    }
                }
            }
        } else {
            // ---- st-only 4x4 tile (lower tiles 24..119) + node covariance ----
            int lid160 = tid - 160;           // 0..95
            int r, c;
            lower_from_idx(24 + lid160, r, c);
            float a_st[4][4] = {};
            #pragma unroll 4
            for (int f = 0; f < DDIM; f++) {
                float4 v;
                float As[4], Bt[4];
                v = *(const float4*)&St_s[f][4 * r]; As[0]=v.x; As[1]=v.y; As[2]=v.z; As[3]=v.w;
                v = *(const float4*)&St_t[f][4 * c]; Bt[0]=v.x; Bt[1]=v.y; Bt[2]=v.z; Bt[3]=v.w;
                #pragma unroll
                for (int i = 0; i < 4; i++)
                    #pragma unroll
                    for (int j = 0; j < 4; j++)
                        a_st[i][j] += As[i] * Bt[j];
            }
            #pragma unroll
            for (int i = 0; i < 4; i++)
                *(float4*)&p2[(4 * r + i) * 64 + 4 * c] =
                    make_float4(a_st[i][0], a_st[i][1], a_st[i][2], a_st[i][3]);

            // node covariance: C[i][j] = dot(St row i, St row j) / 63, symmetric.
            const float inv63 = 1.0f / 63.0f;
            int cbase = (t * NPTS + nn) * (DDIM * DDIM);
            #pragma unroll
            for (int u = 0; u < 2; u++) {
                int cidx = lid160 + 96 * u;
                if (cidx < 136) {
                    int r2, c2;
                    upper_from_idx(cidx, r2, c2);
                    float cs[2][2] = {}, ct[2][2] = {};
                    #pragma unroll 4
                    for (int k = 0; k < 16; k++) {
                        float4 su0 = *(const float4*)&St_s[2 * r2][4 * k];
                        float4 su1 = *(const float4*)&St_s[2 * r2 + 1][4 * k];
                        float4 sv0 = *(const float4*)&St_s[2 * c2][4 * k];
                        float4 sv1 = *(const float4*)&St_s[2 * c2 + 1][4 * k];
                        cs[0][0] += su0.x*sv0.x + su0.y*sv0.y + su0.z*sv0.z + su0.w*sv0.w;
                        cs[0][1] += su0.x*sv1.x + su0.y*sv1.y + su0.z*sv1.z + su0.w*sv1.w;
                        cs[1][0] += su1.x*sv0.x + su1.y*sv0.y + su1.z*sv0.z + su1.w*sv0.w;
                        cs[1][1] += su1.x*sv1.x + su1.y*sv1.y + su1.z*sv1.z + su1.w*sv1.w;
                        float4 tu0 = *(const float4*)&St_t[2 * r2][4 * k];
                        float4 tu1 = *(const float4*)&St_t[2 * r2 + 1][4 * k];
                        float4 tv0 = *(const float4*)&St_t[2 * c2][4 * k];
                        float4 tv1 = *(const float4*)&St_t[2 * c2 + 1][4 * k];
                        ct[0][0] += tu0.x*tv0.x + tu0.y*tv0.y + tu0.z*tv0.z + tu0.w*tv0.w;
                        ct[0][1] += tu0.x*tv1.x + tu0.y*tv1.y + tu0.z*tv1.z + tu0.w*tv1.w;
                        ct[1][0] += tu1.x*tv0.x + tu1.y*tv0.y + tu1.z*tv0.z + tu1.w*tv0.w;
                        ct[1][1] += tu1.x*tv1.x + tu1.y*tv1.y + tu1.z*tv1.z + tu1.w*tv1.w;
                    }
                    #pragma unroll
                    for (int i = 0; i < 2; i++)
                        #pragma unroll
                        for (int j = 0; j < 2; j++) {
                            int o = cbase + (2 * r2 + i) * DDIM + (2 * c2 + j);
                            g_C[0][o] = cs[i][j] * inv63;
                            g_C[1][o] = ct[i][j] * inv63;
                        }
                    if (r2 < c2) {
                        #pragma unroll
                        for (int i = 0; i < 2; i++)
                            #pragma unroll
                            for (int j = 0; j < 2; j++) {
                                int o = cbase + (2 * c2 + j) * DDIM + (2 * r2 + i);
                                g_C[0][o] = cs[i][j] * inv63;
                                g_C[1][o] = ct[i][j] * inv63;
                            }
                    }
                }
            }
        }
    } else if (blk < 136) {
        // ---- L_sca for layer t ----
        int t = blk - 128;
        int base = t * (NPTS * NPTS) + tid;
        float ss = 0.f, sqs = 0.f, st = 0.f, sqt = 0.f;
        #pragma unroll 8
        for (int b = 0; b < BB; b++) {
            float a = Es[b * (HL * NPTS * NPTS) + base];
            ss += a; sqs += a * a;
            float ccc = Et[b * (HL * NPTS * NPTS) + base];
            st += ccc; sqt += ccc * ccc;
        }
        float var_s = (sqs - ss * ss * (1.0f / (float)BB)) * (1.0f / (float)(BB - 1));
        float var_t = (sqt - st * st * (1.0f / (float)BB)) * (1.0f / (float)(BB - 1));
        float d = var_s - var_t;
        red[tid] = d * d * 0.25f;
        __syncthreads();
        for (int s2 = 128; s2 > 0; s2 >>= 1) {
            if (tid < s2) red[tid] += red[tid + s2];
            __syncthreads();
        }
        if (tid == 0) g_sca[t] = red[0] * (1.0f / 256.0f);
    }
    // blocks 136..175: idle in phase 1

    grid_barrier();

    // ================= PHASE 2 (one task per block) =================
    if (blk < 128) {
        // sfa term for (t, n); warp w handles columns j = w, w+8; float4 loads
        int t = blk >> 4, n = blk & 15;
        int w = tid >> 5, lane = tid & 31;
        const float* Cs  = &g_C[0][(t * NPTS + n)     * (DDIM * DDIM)];
        const float* Ct1 = &g_C[1][(t * NPTS + w)     * (DDIM * DDIM)];
        const float* Ct2 = &g_C[1][(t * NPTS + w + 8) * (DDIM * DDIM)];
        float sqs = 0.f, d1 = 0.f, q1 = 0.f, d2 = 0.f, q2 = 0.f;
        #pragma unroll
        for (int kk = 0; kk < 8; kk++) {
            int idx = kk * 128 + lane * 4;
            float4 a  = *(const float4*)&Cs[idx];
            float4 b1 = *(const float4*)&Ct1[idx];
            float4 b2 = *(const float4*)&Ct2[idx];
            sqs += a.x*a.x + a.y*a.y + a.z*a.z + a.w*a.w;
            d1  += a.x*b1.x + a.y*b1.y + a.z*b1.z + a.w*b1.w;
            q1  += b1.x*b1.x + b1.y*b1.y + b1.z*b1.z + b1.w*b1.w;
            d2  += a.x*b2.x + a.y*b2.y + a.z*b2.z + a.w*b2.w;
            q2  += b2.x*b2.x + b2.y*b2.y + b2.z*b2.z + b2.w*b2.w;
        }
        #pragma unroll
        for (int o = 16; o > 0; o >>= 1) {
            sqs += __shfl_xor_sync(0xFFFFFFFFu, sqs, o);
            d1  += __shfl_xor_sync(0xFFFFFFFFu, d1, o);
            q1  += __shfl_xor_sync(0xFFFFFFFFu, q1, o);
            d2  += __shfl_xor_sync(0xFFFFFFFFu, d2, o);
            q2  += __shfl_xor_sync(0xFFFFFFFFu, q2, o);
        }
        if (lane == 0) {
            sm_st[w] = d1;  sm_st[w + 8] = d2;
            sm_tt[w] = q1;  sm_tt[w + 8] = q2;
            if (w == 0) sm_ss = sqs;
        }
        __syncthreads();
        if (tid == 0) {
            float ss = sm_ss;
            float Dsum = 0.f, pos = 0.f;
            #pragma unroll
            for (int j = 0; j < 16; j++) {
                float Dj = (ss + sm_tt[j] - 2.0f * sm_st[j]) * (1.0f / 4096.0f);
                Dsum += Dj;
                if (j == n) pos = Dj;
            }
            float neg = Dsum - pos;
            float ep = expf(pos);
            g_sfa[t * NPTS + n] = logf(ep + neg + 1e-8f) - pos;
        }
    } else {
        // fused Wnum + exo partial: (type, seg)
        // MLP restructure: thread handles (element-group e0, layer tt) -> 8 independent
        // 16-load chains, exchanged via smP, then per-element 9-value reduce.
        int id = blk - 128;                   // 0..47
        int type = id >> 4, seg = id & 15;
        const float* Pbase = &g_P[type * HL * NCHUNK * 4096] + seg * 256;
        int e0 = tid >> 3;                    // 0..31
        int tt = tid & 7;                     // layer
        float v[8];
        #pragma unroll
        for (int p = 0; p < 8; p++) {
            int e = e0 + 32 * p;
            float acc = 0.f;
            #pragma unroll
            for (int c = 0; c < NCHUNK; c++)
                acc += Pbase[(tt * NCHUNK + c) * 4096 + e];
            v[p] = acc;
        }
        #pragma unroll
        for (int p = 0; p < 8; p++) smP[e0 + 32 * p][tt] = v[p];
        __syncthreads();
        float wv[9];
        {
            float esum = 0.f;
            #pragma unroll
            for (int t = 0; t < HL; t++) {
                float x = smP[tid][t];
                wv[t] = x * x;
                esum += x;
            }
            wv[8] = esum * esum;
        }
        int w = tid >> 5, lane = tid & 31;
        #pragma unroll
        for (int k = 0; k < 9; k++) {
            float s = wv[k];
            #pragma unroll
            for (int o = 16; o > 0; o >>= 1)
                s += __shfl_xor_sync(0xFFFFFFFFu, s, o);
            if (lane == 0) smr[w][k] = s;
        }
        __syncthreads();
        if (tid < 9) {
            float s = 0.f;
            #pragma unroll
            for (int ww = 0; ww < 8; ww++) s += smr[ww][tid];
            if (tid < 8) g_Wpart[id * 8 + tid] = s;
            else         g_exo_part[id] = s;
        }
    }

    // ================= PHASE 3: last finisher combines =================
    __syncthreads();
    if (tid == 0) {
        __threadfence();
        unsigned int ticket = atomicAdd(&g_done, 1u);
        sm_last = ((ticket % NBLK) == (NBLK - 1)) ? 1u : 0u;
    }
    __syncthreads();
    if (sm_last && tid < 32) {
        __threadfence();
        int lane = tid;
        const float exo_scale = (float)(1.0 / (3969.0 * 4.0 * 16777216.0));
        const float w_scale   = (float)(1.0 / (3969.0 * 4.0 * 262144.0));
        float val = 0.f;
        if (lane < 8) {
            int t = lane;
            float w0 = 0.f, w1 = 0.f, w2 = 0.f;
            #pragma unroll
            for (int seg = 0; seg < 16; seg++) {
                w0 += g_Wpart[(0 * 16 + seg) * 8 + t];
                w1 += g_Wpart[(1 * 16 + seg) * 8 + t];
                w2 += g_Wpart[(2 * 16 + seg) * 8 + t];
            }
            float W = (w0 + w1 - 2.0f * w2) * w_scale;
            float sfa = 0.f;
            #pragma unroll
            for (int n = 0; n < NPTS; n++) sfa += g_sfa[t * NPTS + n];
            sfa *= (1.0f / (float)NPTS);
            val = W * (0.1f * g_sca[t] + 0.1f * sfa) * (1.0f / (float)HL);
        } else {
            int idA = (lane - 8) * 2, idB = idA + 1;    // 0..47
            float cA = ((idA >> 4) == 2) ? -2.0f : 1.0f;
            float cB = ((idB >> 4) == 2) ? -2.0f : 1.0f;
            val = (g_exo_part[idA] * cA + g_exo_part[idB] * cB) * exo_scale;
        }
        #pragma unroll
        for (int o = 16; o > 0; o >>= 1)
            val += __shfl_xor_sync(0xFFFFFFFFu, val, o);
        if (lane == 0) out[0] = val;
    }
}

// ============================================================
extern "C" void kernel_launch(void* const* d_in, const int* in_sizes, int n_in,
                              void* d_out, int out_size) {
    const float* Zs = (const float*)d_in[0];
    const float* Es = (const float*)d_in[1];
    const float* Zt = (const float*)d_in[2];
    const float* Et = (const float*)d_in[3];
    float* out = (float*)d_out;

    fused_all<<<NBLK, 256>>>(Zs, Es, Zt, Et, out);
}

// round 10
// speedup vs baseline: 1.3633x; 1.3633x over previous
#include <cuda_runtime.h>

// Problem constants
#define BB      64      // batch
#define HL      8       // hat_L
#define NPTS    16      // N
#define DDIM    32      // d
#define FLAYER  512     // N*d
#define FTOT    4096    // hat_L*N*d
#define NCHUNK  16      // feature chunks per layer == nodes (CF == DDIM)
#define NBLK    176     // grid size (all co-resident)
// phase-1: 0..127 gram+cov (t,nn), 128..135 sca, 136..175 idle
// phase-2: 0..127 sfa, 128..175 fused Wnum+exo (type,seg)

// -------- device scratch (no allocations allowed) --------
__device__ float g_P[3 * HL * NCHUNK * 4096];        // chunk Gram partials : 6 MB
__device__ float g_C[2][HL * NPTS * DDIM * DDIM];    // node covariances /63
__device__ float g_Wpart[48 * 8];                    // per-(type,seg) per-layer norm partials
__device__ float g_exo_part[48];                     // per-(type,seg) exo norm partials
__device__ float g_sca[HL];
__device__ float g_sfa[HL * NPTS];
__device__ unsigned int g_barcnt;                    // monotonic barrier ticket
__device__ unsigned int g_done;                      // completion ticket

// Closed-form 16x16 tile-grid triangle enumerations (exact fp32 at boundaries:
// the radicands at segment starts are squares of half-integers / odd integers).
__device__ __forceinline__ void upper_from_idx(int idx, int& r, int& c) {
    float rf = 16.5f - sqrtf(272.25f - 2.0f * (float)idx);
    r = (int)rf;
    c = r + idx - (16 * r - (r * (r - 1)) / 2);
}
__device__ __forceinline__ void lower_from_idx(int idx, int& r, int& c) {
    float rf = (1.0f + sqrtf(1.0f + 8.0f * (float)idx)) * 0.5f;
    r = (int)rf;
    c = idx - (r * (r - 1)) / 2;
}

// Replay-safe grid barrier: monotonic ticket counter, no reset needed.
__device__ __forceinline__ void grid_barrier() {
    __syncthreads();
    if (threadIdx.x == 0) {
        __threadfence();
        unsigned int ticket = atomicAdd(&g_barcnt, 1u);
        unsigned int target = (ticket / NBLK + 1u) * NBLK;
        while (true) {
            unsigned int v;
            asm volatile("ld.acquire.gpu.u32 %0, [%1];"
                         : "=r"(v) : "l"(&g_barcnt));
            if ((int)(v - target) >= 0) break;
            __nanosleep(32);
        }
    }
    __syncthreads();
}

__global__ void __launch_bounds__(256, 2) fused_all(
        const float* __restrict__ Zs, const float* __restrict__ Es,
        const float* __restrict__ Zt, const float* __restrict__ Et,
        float* __restrict__ out) {
    int blk = blockIdx.x, tid = threadIdx.x;

    __shared__ __align__(16) float St_s[DDIM][68];   // [f][b] transposed, padded
    __shared__ __align__(16) float St_t[DDIM][68];
    __shared__ float sm_ps[DDIM * 8], sm_pt[DDIM * 8];   // mean partials
    __shared__ float sm_ms[DDIM], sm_mt[DDIM];           // means
    __shared__ float red[256];
    __shared__ float sm_st[16], sm_tt[16], sm_ss;
    __shared__ float smr[8][9];
    __shared__ unsigned int sm_last;

    // ================= PHASE 1 =================
    if (blk < 128) {
        // slice (t, nn): 64 batch x 32 features, load + center into St (transposed)
        int t = blk >> 4, nn = blk & 15;
        int fbase = t * FLAYER + nn * DDIM;
        int f0 = tid & 31, b0 = tid >> 5;
        float ps = 0.f, pt = 0.f;
        #pragma unroll
        for (int j = 0; j < 8; j++) {
            int b = b0 + 8 * j;
            float vs = Zs[b * FTOT + fbase + f0];
            float vt = Zt[b * FTOT + fbase + f0];
            St_s[f0][b] = vs; ps += vs;
            St_t[f0][b] = vt; pt += vt;
        }
        sm_ps[f0 * 8 + b0] = ps;
        sm_pt[f0 * 8 + b0] = pt;
        __syncthreads();
        if (tid < 64) {                       // reduce mean partials
            int f = tid & 31;
            float* P = (tid < 32) ? sm_ps : sm_pt;
            float m = 0.f;
            #pragma unroll
            for (int j = 0; j < 8; j++) m += P[f * 8 + j];
            m *= (1.0f / (float)BB);
            if (tid < 32) sm_ms[f] = m; else sm_mt[f] = m;
        }
        __syncthreads();
        {                                      // subtract means
            float ms = sm_ms[f0], mt = sm_mt[f0];
            #pragma unroll
            for (int j = 0; j < 8; j++) {
                int b = b0 + 8 * j;
                St_s[f0][b] -= ms;
                St_t[f0][b] -= mt;
            }
        }
        __syncthreads();

        float* p0 = &g_P[((0 * HL + t) * NCHUNK + nn) * 4096];
        float* p1 = &g_P[((1 * HL + t) * NCHUNK + nn) * 4096];
        float* p2 = &g_P[((2 * HL + t) * NCHUNK + nn) * 4096];
        int w = tid >> 5;

        if (w < 5) {
            // ---- 3-type 4x4 tile: 136 upper tiles + 24 padding (lower, st-store-only) ----
            int r, c;
            bool is_upper = (tid < 136);
            if (is_upper) upper_from_idx(tid, r, c);
            else          lower_from_idx(tid - 136, r, c);

            float a_ss[4][4] = {}, a_tt[4][4] = {}, a_st[4][4] = {};
            #pragma unroll 4
            for (int f = 0; f < DDIM; f++) {
                float4 v;
                float As[4], Bs[4], At[4], Bt[4];
                v = *(const float4*)&St_s[f][4 * r]; As[0]=v.x; As[1]=v.y; As[2]=v.z; As[3]=v.w;
                v = *(const float4*)&St_s[f][4 * c]; Bs[0]=v.x; Bs[1]=v.y; Bs[2]=v.z; Bs[3]=v.w;
                v = *(const float4*)&St_t[f][4 * r]; At[0]=v.x; At[1]=v.y; At[2]=v.z; At[3]=v.w;
                v = *(const float4*)&St_t[f][4 * c]; Bt[0]=v.x; Bt[1]=v.y; Bt[2]=v.z; Bt[3]=v.w;
                #pragma unroll
                for (int i = 0; i < 4; i++)
                    #pragma unroll
                    for (int j = 0; j < 4; j++) {
                        a_ss[i][j] += As[i] * Bs[j];
                        a_tt[i][j] += At[i] * Bt[j];
                        a_st[i][j] += As[i] * Bt[j];
                    }
            }
            // st stored always (st not symmetric; padding slots own their lower tile)
            #pragma unroll
            for (int i = 0; i < 4; i++)
                *(float4*)&p2[(4 * r + i) * 64 + 4 * c] =
                    make_float4(a_st[i][0], a_st[i][1], a_st[i][2], a_st[i][3]);
            if (is_upper) {
                #pragma unroll
                for (int i = 0; i < 4; i++) {
                    int o = (4 * r + i) * 64 + 4 * c;
                    *(float4*)&p0[o] = make_float4(a_ss[i][0], a_ss[i][1], a_ss[i][2], a_ss[i][3]);
                    *(float4*)&p1[o] = make_float4(a_tt[i][0], a_tt[i][1], a_tt[i][2], a_tt[i][3]);
                }
                if (r < c) {                   // mirror (bitwise-equal values)
                    #pragma unroll
                    for (int j = 0; j < 4; j++) {
                        int o = (4 * c + j) * 64 + 4 * r;
                        *(float4*)&p0[o] = make_float4(a_ss[0][j], a_ss[1][j], a_ss[2][j], a_ss[3][j]);
                        *(float4*)&p1[o] = make_float4(a_tt[0][j], a_tt[1][j], a_tt[2][j], a_tt[3][j]);
                    }
                }
            }
        } else {
            // ---- st-only 4x4 tile (lower tiles 24..119) + node covariance ----
            int lid160 = tid - 160;           // 0..95
            int r, c;
            lower_from_idx(24 + lid160, r, c);
            float a_st[4][4] = {};
            #pragma unroll 4
            for (int f = 0; f < DDIM; f++) {
                float4 v;
                float As[4], Bt[4];
                v = *(const float4*)&St_s[f][4 * r]; As[0]=v.x; As[1]=v.y; As[2]=v.z; As[3]=v.w;
                v = *(const float4*)&St_t[f][4 * c]; Bt[0]=v.x; Bt[1]=v.y; Bt[2]=v.z; Bt[3]=v.w;
                #pragma unroll
                for (int i = 0; i < 4; i++)
                    #pragma unroll
                    for (int j = 0; j < 4; j++)
                        a_st[i][j] += As[i] * Bt[j];
            }
            #pragma unroll
            for (int i = 0; i < 4; i++)
                *(float4*)&p2[(4 * r + i) * 64 + 4 * c] =
                    make_float4(a_st[i][0], a_st[i][1], a_st[i][2], a_st[i][3]);

            // node covariance: C[i][j] = dot(St row i, St row j) / 63, symmetric.
            const float inv63 = 1.0f / 63.0f;
            int cbase = (t * NPTS + nn) * (DDIM * DDIM);
            #pragma unroll
            for (int u = 0; u < 2; u++) {
                int cidx = lid160 + 96 * u;
                if (cidx < 136) {
                    int r2, c2;
                    upper_from_idx(cidx, r2, c2);
                    float cs[2][2] = {}, ct[2][2] = {};
                    #pragma unroll 4
                    for (int k = 0; k < 16; k++) {
                        float4 su0 = *(const float4*)&St_s[2 * r2][4 * k];
                        float4 su1 = *(const float4*)&St_s[2 * r2 + 1][4 * k];
                        float4 sv0 = *(const float4*)&St_s[2 * c2][4 * k];
                        float4 sv1 = *(const float4*)&St_s[2 * c2 + 1][4 * k];
                        cs[0][0] += su0.x*sv0.x + su0.y*sv0.y + su0.z*sv0.z + su0.w*sv0.w;
                        cs[0][1] += su0.x*sv1.x + su0.y*sv1.y + su0.z*sv1.z + su0.w*sv1.w;
                        cs[1][0] += su1.x*sv0.x + su1.y*sv0.y + su1.z*sv0.z + su1.w*sv0.w;
                        cs[1][1] += su1.x*sv1.x + su1.y*sv1.y + su1.z*sv1.z + su1.w*sv1.w;
                        float4 tu0 = *(const float4*)&St_t[2 * r2][4 * k];
                        float4 tu1 = *(const float4*)&St_t[2 * r2 + 1][4 * k];
                        float4 tv0 = *(const float4*)&St_t[2 * c2][4 * k];
                        float4 tv1 = *(const float4*)&St_t[2 * c2 + 1][4 * k];
                        ct[0][0] += tu0.x*tv0.x + tu0.y*tv0.y + tu0.z*tv0.z + tu0.w*tv0.w;
                        ct[0][1] += tu0.x*tv1.x + tu0.y*tv1.y + tu0.z*tv1.z + tu0.w*tv1.w;
                        ct[1][0] += tu1.x*tv0.x + tu1.y*tv0.y + tu1.z*tv0.z + tu1.w*tv0.w;
                        ct[1][1] += tu1.x*tv1.x + tu1.y*tv1.y + tu1.z*tv1.z + tu1.w*tv1.w;
                    }
                    #pragma unroll
                    for (int i = 0; i < 2; i++)
                        #pragma unroll
                        for (int j = 0; j < 2; j++) {
                            int o = cbase + (2 * r2 + i) * DDIM + (2 * c2 + j);
                            g_C[0][o] = cs[i][j] * inv63;
                            g_C[1][o] = ct[i][j] * inv63;
                        }
                    if (r2 < c2) {
                        #pragma unroll
                        for (int i = 0; i < 2; i++)
                            #pragma unroll
                            for (int j = 0; j < 2; j++) {
                                int o = cbase + (2 * c2 + j) * DDIM + (2 * r2 + i);
                                g_C[0][o] = cs[i][j] * inv63;
                                g_C[1][o] = ct[i][j] * inv63;
                            }
                    }
                }
            }
        }
    } else if (blk < 136) {
        // ---- L_sca for layer t ----
        int t = blk - 128;
        int base = t * (NPTS * NPTS) + tid;
        float ss = 0.f, sqs = 0.f, st = 0.f, sqt = 0.f;
        #pragma unroll 8
        for (int b = 0; b < BB; b++) {
            float a = Es[b * (HL * NPTS * NPTS) + base];
            ss += a; sqs += a * a;
            float ccc = Et[b * (HL * NPTS * NPTS) + base];
            st += ccc; sqt += ccc * ccc;
        }
        float var_s = (sqs - ss * ss * (1.0f / (float)BB)) * (1.0f / (float)(BB - 1));
        float var_t = (sqt - st * st * (1.0f / (float)BB)) * (1.0f / (float)(BB - 1));
        float d = var_s - var_t;
        red[tid] = d * d * 0.25f;
        __syncthreads();
        for (int s2 = 128; s2 > 0; s2 >>= 1) {
            if (tid < s2) red[tid] += red[tid + s2];
            __syncthreads();
        }
        if (tid == 0) g_sca[t] = red[0] * (1.0f / 256.0f);
    }
    // blocks 136..175: idle in phase 1

    grid_barrier();

    // ================= PHASE 2 (one task per block) =================
    if (blk < 128) {
        // sfa term for (t, n); warp w handles columns j = w, w+8; float4 loads
        int t = blk >> 4, n = blk & 15;
        int w = tid >> 5, lane = tid & 31;
        const float* Cs  = &g_C[0][(t * NPTS + n)     * (DDIM * DDIM)];
        const float* Ct1 = &g_C[1][(t * NPTS + w)     * (DDIM * DDIM)];
        const float* Ct2 = &g_C[1][(t * NPTS + w + 8) * (DDIM * DDIM)];
        float sqs = 0.f, d1 = 0.f, q1 = 0.f, d2 = 0.f, q2 = 0.f;
        #pragma unroll
        for (int kk = 0; kk < 8; kk++) {
            int idx = kk * 128 + lane * 4;
            float4 a  = *(const float4*)&Cs[idx];
            float4 b1 = *(const float4*)&Ct1[idx];
            float4 b2 = *(const float4*)&Ct2[idx];
            sqs += a.x*a.x + a.y*a.y + a.z*a.z + a.w*a.w;
            d1  += a.x*b1.x + a.y*b1.y + a.z*b1.z + a.w*b1.w;
            q1  += b1.x*b1.x + b1.y*b1.y + b1.z*b1.z + b1.w*b1.w;
            d2  += a.x*b2.x + a.y*b2.y + a.z*b2.z + a.w*b2.w;
            q2  += b2.x*b2.x + b2.y*b2.y + b2.z*b2.z + b2.w*b2.w;
        }
        #pragma unroll
        for (int o = 16; o > 0; o >>= 1) {
            sqs += __shfl_xor_sync(0xFFFFFFFFu, sqs, o);
            d1  += __shfl_xor_sync(0xFFFFFFFFu, d1, o);
            q1  += __shfl_xor_sync(0xFFFFFFFFu, q1, o);
            d2  += __shfl_xor_sync(0xFFFFFFFFu, d2, o);
            q2  += __shfl_xor_sync(0xFFFFFFFFu, q2, o);
        }
        if (lane == 0) {
            sm_st[w] = d1;  sm_st[w + 8] = d2;
            sm_tt[w] = q1;  sm_tt[w + 8] = q2;
            if (w == 0) sm_ss = sqs;
        }
        __syncthreads();
        if (tid == 0) {
            float ss = sm_ss;
            float Dsum = 0.f, pos = 0.f;
            #pragma unroll
            for (int j = 0; j < 16; j++) {
                float Dj = (ss + sm_tt[j] - 2.0f * sm_st[j]) * (1.0f / 4096.0f);
                Dsum += Dj;
                if (j == n) pos = Dj;
            }
            float neg = Dsum - pos;
            float ep = expf(pos);
            g_sfa[t * NPTS + n] = logf(ep + neg + 1e-8f) - pos;
        }
    } else {
        // fused Wnum + exo partial: (type, seg), element i = seg*256 + tid
        // (coalesced: warp spans 32 contiguous floats; all 128 loads independent)
        int id = blk - 128;                   // 0..47
        int type = id >> 4, seg = id & 15;
        const float* Pbase = &g_P[type * HL * NCHUNK * 4096];
        int i = seg * 256 + tid;
        float e = 0.f;
        float wv[9];
        #pragma unroll
        for (int t = 0; t < HL; t++) {
            float v = 0.f;
            #pragma unroll
            for (int c = 0; c < NCHUNK; c++)
                v += Pbase[(t * NCHUNK + c) * 4096 + i];
            wv[t] = v * v;
            e += v;
        }
        wv[8] = e * e;
        int w = tid >> 5, lane = tid & 31;
        #pragma unroll
        for (int k = 0; k < 9; k++) {
            float s = wv[k];
            #pragma unroll
            for (int o = 16; o > 0; o >>= 1)
                s += __shfl_xor_sync(0xFFFFFFFFu, s, o);
            if (lane == 0) smr[w][k] = s;
        }
        __syncthreads();
        if (tid < 9) {
            float s = 0.f;
            #pragma unroll
            for (int ww = 0; ww < 8; ww++) s += smr[ww][tid];
            if (tid < 8) g_Wpart[id * 8 + tid] = s;
            else         g_exo_part[id] = s;
        }
    }

    // ================= PHASE 3: last finisher combines =================
    __syncthreads();
    if (tid == 0) {
        __threadfence();
        unsigned int ticket = atomicAdd(&g_done, 1u);
        sm_last = ((ticket % NBLK) == (NBLK - 1)) ? 1u : 0u;
    }
    __syncthreads();
    if (sm_last && tid < 32) {
        __threadfence();
        int lane = tid;
        const float exo_scale = (float)(1.0 / (3969.0 * 4.0 * 16777216.0));
        const float w_scale   = (float)(1.0 / (3969.0 * 4.0 * 262144.0));
        float val = 0.f;
        if (lane < 8) {
            int t = lane;
            float w0 = 0.f, w1 = 0.f, w2 = 0.f;
            #pragma unroll
            for (int seg = 0; seg < 16; seg++) {
                w0 += g_Wpart[(0 * 16 + seg) * 8 + t];
                w1 += g_Wpart[(1 * 16 + seg) * 8 + t];
                w2 += g_Wpart[(2 * 16 + seg) * 8 + t];
            }
            float W = (w0 + w1 - 2.0f * w2) * w_scale;
            float sfa = 0.f;
            #pragma unroll
            for (int n = 0; n < NPTS; n++) sfa += g_sfa[t * NPTS + n];
            sfa *= (1.0f / (float)NPTS);
            val = W * (0.1f * g_sca[t] + 0.1f * sfa) * (1.0f / (float)HL);
        } else {
            int idA = (lane - 8) * 2, idB = idA + 1;    // 0..47
            float cA = ((idA >> 4) == 2) ? -2.0f : 1.0f;
            float cB = ((idB >> 4) == 2) ? -2.0f : 1.0f;
            val = (g_exo_part[idA] * cA + g_exo_part[idB] * cB) * exo_scale;
        }
        #pragma unroll
        for (int o = 16; o > 0; o >>= 1)
            val += __shfl_xor_sync(0xFFFFFFFFu, val, o);
        if (lane == 0) out[0] = val;
    }
}

// ============================================================
extern "C" void kernel_launch(void* const* d_in, const int* in_sizes, int n_in,
                              void* d_out, int out_size) {
    const float* Zs = (const float*)d_in[0];
    const float* Es = (const float*)d_in[1];
    const float* Zt = (const float*)d_in[2];
    const float* Et = (const float*)d_in[3];
    float* out = (float*)d_out;

    fused_all<<<NBLK, 256>>>(Zs, Es, Zt, Et, out);
}

// round 11
// speedup vs baseline: 1.3681x; 1.0035x over previous
#include <cuda_runtime.h>

// Problem constants
#define BB      64      // batch
#define HL      8       // hat_L
#define NPTS    16      // N
#define DDIM    32      // d
#define FLAYER  512     // N*d
#define FTOT    4096    // hat_L*N*d
#define NCHUNK  16      // feature chunks per layer == nodes (CF == DDIM)
#define NBLK    184     // 128 heavy + 8 sca + 48 Wnum/exo
// blk 0..127  : gram+cov for (t,nn), then wait layer counter, then sfa(t,nn)
// blk 128..135: sca layer t
// blk 136..183: fused Wnum+exo (type,seg), gated on gram counter

// -------- device scratch (no allocations allowed) --------
__device__ float g_P[3 * HL * NCHUNK * 4096];        // chunk Gram partials : 6 MB
__device__ float g_Ct[HL * NPTS * DDIM * DDIM];      // TARGET node covariances /63
__device__ float g_Wpart[48 * 8];                    // per-(type,seg) per-layer norm partials
__device__ float g_exo_part[48];                     // per-(type,seg) exo norm partials
__device__ float g_sca[HL];
__device__ float g_sfa[HL * NPTS];
__device__ unsigned int g_cnt_layer[HL];             // monotonic per-layer producer counters
__device__ unsigned int g_cnt_gram;                  // monotonic gram-producer counter
__device__ unsigned int g_wcnt;                      // waiter ticket counter
__device__ unsigned int g_done;                      // completion ticket

// Closed-form 16x16 tile-grid triangle enumerations (exact fp32 at boundaries).
__device__ __forceinline__ void upper_from_idx(int idx, int& r, int& c) {
    float rf = 16.5f - sqrtf(272.25f - 2.0f * (float)idx);
    r = (int)rf;
    c = r + idx - (16 * r - (r * (r - 1)) / 2);
}
__device__ __forceinline__ void lower_from_idx(int idx, int& r, int& c) {
    float rf = (1.0f + sqrtf(1.0f + 8.0f * (float)idx)) * 0.5f;
    r = (int)rf;
    c = idx - (r * (r - 1)) / 2;
}

// Acquire-spin until *p >= target (monotonic counter).
__device__ __forceinline__ void spin_until(unsigned int* p, unsigned int target) {
    while (true) {
        unsigned int v;
        asm volatile("ld.acquire.gpu.u32 %0, [%1];" : "=r"(v) : "l"(p));
        if ((int)(v - target) >= 0) break;
        __nanosleep(32);
    }
}

__global__ void __launch_bounds__(256, 2) fused_all(
        const float* __restrict__ Zs, const float* __restrict__ Es,
        const float* __restrict__ Zt, const float* __restrict__ Et,
        float* __restrict__ out) {
    int blk = blockIdx.x, tid = threadIdx.x;

    __shared__ __align__(16) float St_s[DDIM][68];   // [f][b] transposed, padded
    __shared__ __align__(16) float St_t[DDIM][68];
    __shared__ __align__(16) float Csm[DDIM * DDIM]; // own SOURCE covariance /63
    __shared__ float sm_ps[DDIM * 8], sm_pt[DDIM * 8];
    __shared__ float sm_ms[DDIM], sm_mt[DDIM];
    __shared__ float red[256];
    __shared__ float sm_st[16], sm_tt[16], sm_ss;
    __shared__ float smr[8][9];
    __shared__ unsigned int sm_last;

    if (blk < 128) {
        // ============ heavy block (t, nn): gram + cov, then sfa ============
        int t = blk >> 4, nn = blk & 15;
        int fbase = t * FLAYER + nn * DDIM;
        int f0 = tid & 31, b0 = tid >> 5;
        float ps = 0.f, pt = 0.f;
        #pragma unroll
        for (int j = 0; j < 8; j++) {
            int b = b0 + 8 * j;
            float vs = Zs[b * FTOT + fbase + f0];
            float vt = Zt[b * FTOT + fbase + f0];
            St_s[f0][b] = vs; ps += vs;
            St_t[f0][b] = vt; pt += vt;
        }
        sm_ps[f0 * 8 + b0] = ps;
        sm_pt[f0 * 8 + b0] = pt;
        __syncthreads();
        if (tid < 64) {
            int f = tid & 31;
            float* P = (tid < 32) ? sm_ps : sm_pt;
            float m = 0.f;
            #pragma unroll
            for (int j = 0; j < 8; j++) m += P[f * 8 + j];
            m *= (1.0f / (float)BB);
            if (tid < 32) sm_ms[f] = m; else sm_mt[f] = m;
        }
        __syncthreads();
        {
            float ms = sm_ms[f0], mt = sm_mt[f0];
            #pragma unroll
            for (int j = 0; j < 8; j++) {
                int b = b0 + 8 * j;
                St_s[f0][b] -= ms;
                St_t[f0][b] -= mt;
            }
        }
        __syncthreads();

        float* p0 = &g_P[((0 * HL + t) * NCHUNK + nn) * 4096];
        float* p1 = &g_P[((1 * HL + t) * NCHUNK + nn) * 4096];
        float* p2 = &g_P[((2 * HL + t) * NCHUNK + nn) * 4096];
        int w = tid >> 5;

        if (w < 5) {
            // 3-type 4x4 tile: 136 upper + 24 padding (lower, st-only)
            int r, c;
            bool is_upper = (tid < 136);
            if (is_upper) upper_from_idx(tid, r, c);
            else          lower_from_idx(tid - 136, r, c);

            float a_ss[4][4] = {}, a_tt[4][4] = {}, a_st[4][4] = {};
            #pragma unroll 4
            for (int f = 0; f < DDIM; f++) {
                float4 v;
                float As[4], Bs[4], At[4], Bt[4];
                v = *(const float4*)&St_s[f][4 * r]; As[0]=v.x; As[1]=v.y; As[2]=v.z; As[3]=v.w;
                v = *(const float4*)&St_s[f][4 * c]; Bs[0]=v.x; Bs[1]=v.y; Bs[2]=v.z; Bs[3]=v.w;
                v = *(const float4*)&St_t[f][4 * r]; At[0]=v.x; At[1]=v.y; At[2]=v.z; At[3]=v.w;
                v = *(const float4*)&St_t[f][4 * c]; Bt[0]=v.x; Bt[1]=v.y; Bt[2]=v.z; Bt[3]=v.w;
                #pragma unroll
                for (int i = 0; i < 4; i++)
                    #pragma unroll
                    for (int j = 0; j < 4; j++) {
                        a_ss[i][j] += As[i] * Bs[j];
                        a_tt[i][j] += At[i] * Bt[j];
                        a_st[i][j] += As[i] * Bt[j];
                    }
            }
            #pragma unroll
            for (int i = 0; i < 4; i++)
                *(float4*)&p2[(4 * r + i) * 64 + 4 * c] =
                    make_float4(a_st[i][0], a_st[i][1], a_st[i][2], a_st[i][3]);
            if (is_upper) {
                #pragma unroll
                for (int i = 0; i < 4; i++) {
                    int o = (4 * r + i) * 64 + 4 * c;
                    *(float4*)&p0[o] = make_float4(a_ss[i][0], a_ss[i][1], a_ss[i][2], a_ss[i][3]);
                    *(float4*)&p1[o] = make_float4(a_tt[i][0], a_tt[i][1], a_tt[i][2], a_tt[i][3]);
                }
                if (r < c) {
                    #pragma unroll
                    for (int j = 0; j < 4; j++) {
                        int o = (4 * c + j) * 64 + 4 * r;
                        *(float4*)&p0[o] = make_float4(a_ss[0][j], a_ss[1][j], a_ss[2][j], a_ss[3][j]);
                        *(float4*)&p1[o] = make_float4(a_tt[0][j], a_tt[1][j], a_tt[2][j], a_tt[3][j]);
                    }
                }
            }
        } else {
            // st-only 4x4 tile (lower tiles 24..119) + node covariance
            int lid160 = tid - 160;           // 0..95
            int r, c;
            lower_from_idx(24 + lid160, r, c);
            float a_st[4][4] = {};
            #pragma unroll 4
            for (int f = 0; f < DDIM; f++) {
                float4 v;
                float As[4], Bt[4];
                v = *(const float4*)&St_s[f][4 * r]; As[0]=v.x; As[1]=v.y; As[2]=v.z; As[3]=v.w;
                v = *(const float4*)&St_t[f][4 * c]; Bt[0]=v.x; Bt[1]=v.y; Bt[2]=v.z; Bt[3]=v.w;
                #pragma unroll
                for (int i = 0; i < 4; i++)
                    #pragma unroll
                    for (int j = 0; j < 4; j++)
                        a_st[i][j] += As[i] * Bt[j];
            }
            #pragma unroll
            for (int i = 0; i < 4; i++)
                *(float4*)&p2[(4 * r + i) * 64 + 4 * c] =
                    make_float4(a_st[i][0], a_st[i][1], a_st[i][2], a_st[i][3]);

            // covariance: source -> smem only; target -> gmem (consumed by all sfa of layer t)
            const float inv63 = 1.0f / 63.0f;
            int cbase = (t * NPTS + nn) * (DDIM * DDIM);
            #pragma unroll
            for (int u = 0; u < 2; u++) {
                int cidx = lid160 + 96 * u;
                if (cidx < 136) {
                    int r2, c2;
                    upper_from_idx(cidx, r2, c2);
                    float cs[2][2] = {}, ct[2][2] = {};
                    #pragma unroll 4
                    for (int k = 0; k < 16; k++) {
                        float4 su0 = *(const float4*)&St_s[2 * r2][4 * k];
                        float4 su1 = *(const float4*)&St_s[2 * r2 + 1][4 * k];
                        float4 sv0 = *(const float4*)&St_s[2 * c2][4 * k];
                        float4 sv1 = *(const float4*)&St_s[2 * c2 + 1][4 * k];
                        cs[0][0] += su0.x*sv0.x + su0.y*sv0.y + su0.z*sv0.z + su0.w*sv0.w;
                        cs[0][1] += su0.x*sv1.x + su0.y*sv1.y + su0.z*sv1.z + su0.w*sv1.w;
                        cs[1][0] += su1.x*sv0.x + su1.y*sv0.y + su1.z*sv0.z + su1.w*sv0.w;
                        cs[1][1] += su1.x*sv1.x + su1.y*sv1.y + su1.z*sv1.z + su1.w*sv1.w;
                        float4 tu0 = *(const float4*)&St_t[2 * r2][4 * k];
                        float4 tu1 = *(const float4*)&St_t[2 * r2 + 1][4 * k];
                        float4 tv0 = *(const float4*)&St_t[2 * c2][4 * k];
                        float4 tv1 = *(const float4*)&St_t[2 * c2 + 1][4 * k];
                        ct[0][0] += tu0.x*tv0.x + tu0.y*tv0.y + tu0.z*tv0.z + tu0.w*tv0.w;
                        ct[0][1] += tu0.x*tv1.x + tu0.y*tv1.y + tu0.z*tv1.z + tu0.w*tv1.w;
                        ct[1][0] += tu1.x*tv0.x + tu1.y*tv0.y + tu1.z*tv0.z + tu1.w*tv0.w;
                        ct[1][1] += tu1.x*tv1.x + tu1.y*tv1.y + tu1.z*tv1.z + tu1.w*tv1.w;
                    }
                    #pragma unroll
                    for (int i = 0; i < 2; i++)
                        #pragma unroll
                        for (int j = 0; j < 2; j++) {
                            int oi = (2 * r2 + i) * DDIM + (2 * c2 + j);
                            Csm[oi] = cs[i][j] * inv63;
                            g_Ct[cbase + oi] = ct[i][j] * inv63;
                        }
                    if (r2 < c2) {
                        #pragma unroll
                        for (int i = 0; i < 2; i++)
                            #pragma unroll
                            for (int j = 0; j < 2; j++) {
                                int oi = (2 * c2 + j) * DDIM + (2 * r2 + i);
                                Csm[oi] = cs[i][j] * inv63;
                                g_Ct[cbase + oi] = ct[i][j] * inv63;
                            }
                    }
                }
            }
        }

        // -------- publish + wait for layer-t producers --------
        __syncthreads();
        if (tid == 0) {
            __threadfence();
            atomicAdd(&g_cnt_gram, 1u);
            unsigned int tk = atomicAdd(&g_cnt_layer[t], 1u);
            spin_until(&g_cnt_layer[t], (tk / 16u + 1u) * 16u);
        }
        __syncthreads();

        // -------- sfa(t, nn): Cs from smem, Ct from gmem --------
        {
            int n = nn;
            int lane = tid & 31;
            const float* Ct1 = &g_Ct[(t * NPTS + w)     * (DDIM * DDIM)];
            const float* Ct2 = &g_Ct[(t * NPTS + w + 8) * (DDIM * DDIM)];
            float sqs = 0.f, d1 = 0.f, q1 = 0.f, d2 = 0.f, q2 = 0.f;
            #pragma unroll
            for (int kk = 0; kk < 8; kk++) {
                int idx = kk * 128 + lane * 4;
                float4 a  = *(const float4*)&Csm[idx];
                float4 b1 = *(const float4*)&Ct1[idx];
                float4 b2 = *(const float4*)&Ct2[idx];
                sqs += a.x*a.x + a.y*a.y + a.z*a.z + a.w*a.w;
                d1  += a.x*b1.x + a.y*b1.y + a.z*b1.z + a.w*b1.w;
                q1  += b1.x*b1.x + b1.y*b1.y + b1.z*b1.z + b1.w*b1.w;
                d2  += a.x*b2.x + a.y*b2.y + a.z*b2.z + a.w*b2.w;
                q2  += b2.x*b2.x + b2.y*b2.y + b2.z*b2.z + b2.w*b2.w;
            }
            #pragma unroll
            for (int o = 16; o > 0; o >>= 1) {
                sqs += __shfl_xor_sync(0xFFFFFFFFu, sqs, o);
                d1  += __shfl_xor_sync(0xFFFFFFFFu, d1, o);
                q1  += __shfl_xor_sync(0xFFFFFFFFu, q1, o);
                d2  += __shfl_xor_sync(0xFFFFFFFFu, d2, o);
                q2  += __shfl_xor_sync(0xFFFFFFFFu, q2, o);
            }
            if (lane == 0) {
                sm_st[w] = d1;  sm_st[w + 8] = d2;
                sm_tt[w] = q1;  sm_tt[w + 8] = q2;
                if (w == 0) sm_ss = sqs;
            }
            __syncthreads();
            if (tid == 0) {
                float ss = sm_ss;
                float Dsum = 0.f, pos = 0.f;
                #pragma unroll
                for (int j = 0; j < 16; j++) {
                    float Dj = (ss + sm_tt[j] - 2.0f * sm_st[j]) * (1.0f / 4096.0f);
                    Dsum += Dj;
                    if (j == n) pos = Dj;
                }
                float neg = Dsum - pos;
                float ep = expf(pos);
                g_sfa[t * NPTS + n] = logf(ep + neg + 1e-8f) - pos;
            }
        }
    } else if (blk < 136) {
        // ============ L_sca for layer t ============
        int t = blk - 128;
        int base = t * (NPTS * NPTS) + tid;
        float ss = 0.f, sqs = 0.f, st = 0.f, sqt = 0.f;
        #pragma unroll 8
        for (int b = 0; b < BB; b++) {
            float a = Es[b * (HL * NPTS * NPTS) + base];
            ss += a; sqs += a * a;
            float ccc = Et[b * (HL * NPTS * NPTS) + base];
            st += ccc; sqt += ccc * ccc;
        }
        float var_s = (sqs - ss * ss * (1.0f / (float)BB)) * (1.0f / (float)(BB - 1));
        float var_t = (sqt - st * st * (1.0f / (float)BB)) * (1.0f / (float)(BB - 1));
        float d = var_s - var_t;
        red[tid] = d * d * 0.25f;
        __syncthreads();
        for (int s2 = 128; s2 > 0; s2 >>= 1) {
            if (tid < s2) red[tid] += red[tid + s2];
            __syncthreads();
        }
        if (tid == 0) g_sca[t] = red[0] * (1.0f / 256.0f);
    } else {
        // ============ fused Wnum + exo (type, seg), gated on gram counter ============
        if (tid == 0) {
            unsigned int tk = atomicAdd(&g_wcnt, 1u);
            spin_until(&g_cnt_gram, (tk / 48u + 1u) * 128u);
        }
        __syncthreads();

        int id = blk - 136;                   // 0..47
        int type = id >> 4, seg = id & 15;
        const float* Pbase = &g_P[type * HL * NCHUNK * 4096];
        int i = seg * 256 + tid;
        float e = 0.f;
        float wv[9];
        #pragma unroll
        for (int t = 0; t < HL; t++) {
            float v = 0.f;
            #pragma unroll
            for (int c = 0; c < NCHUNK; c++)
                v += Pbase[(t * NCHUNK + c) * 4096 + i];
            wv[t] = v * v;
            e += v;
        }
        wv[8] = e * e;
        int w = tid >> 5, lane = tid & 31;
        #pragma unroll
        for (int k = 0; k < 9; k++) {
            float s = wv[k];
            #pragma unroll
            for (int o = 16; o > 0; o >>= 1)
                s += __shfl_xor_sync(0xFFFFFFFFu, s, o);
            if (lane == 0) smr[w][k] = s;
        }
        __syncthreads();
        if (tid < 9) {
            float s = 0.f;
            #pragma unroll
            for (int ww = 0; ww < 8; ww++) s += smr[ww][tid];
            if (tid < 8) g_Wpart[id * 8 + tid] = s;
            else         g_exo_part[id] = s;
        }
    }

    // ================= finisher: last done-ticket combines =================
    __syncthreads();
    if (tid == 0) {
        __threadfence();
        unsigned int ticket = atomicAdd(&g_done, 1u);
        sm_last = ((ticket % NBLK) == (NBLK - 1)) ? 1u : 0u;
    }
    __syncthreads();
    if (sm_last && tid < 32) {
        __threadfence();
        int lane = tid;
        const float exo_scale = (float)(1.0 / (3969.0 * 4.0 * 16777216.0));
        const float w_scale   = (float)(1.0 / (3969.0 * 4.0 * 262144.0));
        float val = 0.f;
        if (lane < 8) {
            int t = lane;
            float w0 = 0.f, w1 = 0.f, w2 = 0.f;
            #pragma unroll
            for (int seg = 0; seg < 16; seg++) {
                w0 += g_Wpart[(0 * 16 + seg) * 8 + t];
                w1 += g_Wpart[(1 * 16 + seg) * 8 + t];
                w2 += g_Wpart[(2 * 16 + seg) * 8 + t];
            }
            float W = (w0 + w1 - 2.0f * w2) * w_scale;
            float sfa = 0.f;
            #pragma unroll
            for (int n = 0; n < NPTS; n++) sfa += g_sfa[t * NPTS + n];
            sfa *= (1.0f / (float)NPTS);
            val = W * (0.1f * g_sca[t] + 0.1f * sfa) * (1.0f / (float)HL);
        } else {
            int idA = (lane - 8) * 2, idB = idA + 1;    // 0..47
            float cA = ((idA >> 4) == 2) ? -2.0f : 1.0f;
            float cB = ((idB >> 4) == 2) ? -2.0f : 1.0f;
            val = (g_exo_part[idA] * cA + g_exo_part[idB] * cB) * exo_scale;
        }
        #pragma unroll
        for (int o = 16; o > 0; o >>= 1)
            val += __shfl_xor_sync(0xFFFFFFFFu, val, o);
        if (lane == 0) out[0] = val;
    }
}

// ============================================================
extern "C" void kernel_launch(void* const* d_in, const int* in_sizes, int n_in,
                              void* d_out, int out_size) {
    const float* Zs = (const float*)d_in[0];
    const float* Es = (const float*)d_in[1];
    const float* Zt = (const float*)d_in[2];
    const float* Et = (const float*)d_in[3];
    float* out = (float*)d_out;

    fused_all<<<NBLK, 256>>>(Zs, Es, Zt, Et, out);
}